// round 1
// baseline (speedup 1.0000x reference)
#include <cuda_runtime.h>
#include <math.h>

#define T_SEQ   4096
#define C_DIM   768
#define H_NUM   12
#define D_HEAD  64
#define QKV_N   (3 * C_DIM)

// Scratch (allocation-free): qkv = [T, 3C], y = [T, C] (head-interleaved, same as C layout)
__device__ float g_qkv[T_SEQ * QKV_N];
__device__ float g_y[T_SEQ * C_DIM];

// ----------------------------------------------------------------------------
// Tiled SGEMM with fused bias: C[M,N] = A[M,K] @ B[K,N] + bias[N]
// BM=BN=128, BK=16, 256 threads, 8x8 register microtile. All dims divide tiles.
// ----------------------------------------------------------------------------
__global__ __launch_bounds__(256) void sgemm_bias_kernel(
    const float* __restrict__ A, const float* __restrict__ B,
    const float* __restrict__ bias, float* __restrict__ Cm,
    int M, int N, int K)
{
    constexpr int BM = 128, BN = 128, BK = 16, TM = 8, TN = 8;
    __shared__ float As[BK][BM];
    __shared__ float Bs[BK][BN];

    const int tid  = threadIdx.x;
    const int brow = blockIdx.y * BM;
    const int bcol = blockIdx.x * BN;
    const int trow = (tid / 16) * TM;
    const int tcol = (tid % 16) * TN;

    float acc[TM][TN];
#pragma unroll
    for (int i = 0; i < TM; i++)
#pragma unroll
        for (int j = 0; j < TN; j++) acc[i][j] = 0.0f;

    for (int k0 = 0; k0 < K; k0 += BK) {
        // Load A tile (128x16), transposed into As[k][m]
#pragma unroll
        for (int i = 0; i < 2; i++) {
            int m = (tid >> 2) + i * 64;
            int k = (tid & 3) * 4;
            float4 v = *(const float4*)&A[(size_t)(brow + m) * K + k0 + k];
            As[k + 0][m] = v.x;
            As[k + 1][m] = v.y;
            As[k + 2][m] = v.z;
            As[k + 3][m] = v.w;
        }
        // Load B tile (16x128) directly
#pragma unroll
        for (int i = 0; i < 2; i++) {
            int k = (tid >> 5) + i * 8;
            int n = (tid & 31) * 4;
            *(float4*)&Bs[k][n] = *(const float4*)&B[(size_t)(k0 + k) * N + bcol + n];
        }
        __syncthreads();

#pragma unroll
        for (int kk = 0; kk < BK; kk++) {
            float ra[TM], rb[TN];
#pragma unroll
            for (int i = 0; i < TM; i++) ra[i] = As[kk][trow + i];
#pragma unroll
            for (int j = 0; j < TN; j++) rb[j] = Bs[kk][tcol + j];
#pragma unroll
            for (int i = 0; i < TM; i++)
#pragma unroll
                for (int j = 0; j < TN; j++)
                    acc[i][j] = fmaf(ra[i], rb[j], acc[i][j]);
        }
        __syncthreads();
    }

    // Epilogue: add bias, vectorized store
#pragma unroll
    for (int i = 0; i < TM; i++) {
#pragma unroll
        for (int j = 0; j < TN; j += 4) {
            float4 v;
            v.x = acc[i][j + 0] + bias[bcol + tcol + j + 0];
            v.y = acc[i][j + 1] + bias[bcol + tcol + j + 1];
            v.z = acc[i][j + 2] + bias[bcol + tcol + j + 2];
            v.w = acc[i][j + 3] + bias[bcol + tcol + j + 3];
            *(float4*)&Cm[(size_t)(brow + trow + i) * N + bcol + tcol + j] = v;
        }
    }
}

// ----------------------------------------------------------------------------
// Causal flash attention, fp32. One query per thread, 128 queries per block.
// grid = (T/128, H). K/V tiles (32 x 64) staged in SMEM; q and acc in registers.
// Online softmax; q pre-scaled by 1/sqrt(D).
// ----------------------------------------------------------------------------
__global__ __launch_bounds__(128) void flash_attn_kernel()
{
    const int h  = blockIdx.y;
    const int qi = blockIdx.x * 128 + threadIdx.x;
    const float scale = 0.125f;  // 1/sqrt(64)

    float q[D_HEAD];
    {
        const float* qptr = &g_qkv[(size_t)qi * QKV_N + h * D_HEAD];
#pragma unroll
        for (int d = 0; d < D_HEAD; d += 4) {
            float4 v = *(const float4*)&qptr[d];
            q[d + 0] = v.x * scale;
            q[d + 1] = v.y * scale;
            q[d + 2] = v.z * scale;
            q[d + 3] = v.w * scale;
        }
    }

    float acc[D_HEAD];
#pragma unroll
    for (int d = 0; d < D_HEAD; d++) acc[d] = 0.0f;
    float m = -1e30f;
    float l = 0.0f;

    __shared__ float Ks[32][D_HEAD];
    __shared__ float Vs[32][D_HEAD];

    const int kend = blockIdx.x * 128 + 128;  // keys needed by last query in block
    for (int kt = 0; kt < kend; kt += 32) {
        // Cooperative load of 32x64 K and V tiles (float4, coalesced)
#pragma unroll
        for (int i = 0; i < 4; i++) {
            int lin = threadIdx.x + i * 128;
            int r = lin >> 4;
            int c = (lin & 15) * 4;
            const float* base = &g_qkv[(size_t)(kt + r) * QKV_N + h * D_HEAD + c];
            *(float4*)&Ks[r][c] = *(const float4*)&base[C_DIM];
            *(float4*)&Vs[r][c] = *(const float4*)&base[2 * C_DIM];
        }
        __syncthreads();

        int jmax = qi - kt + 1;        // causal: include diagonal
        if (jmax > 32) jmax = 32;
        for (int j = 0; j < jmax; j++) {
            // dot(q, K[j]) with 8 partial sums to break the FMA dep chain
            float p[8];
#pragma unroll
            for (int t = 0; t < 8; t++) p[t] = 0.0f;
#pragma unroll
            for (int d = 0; d < D_HEAD; d += 8) {
#pragma unroll
                for (int t = 0; t < 8; t++)
                    p[t] = fmaf(q[d + t], Ks[j][d + t], p[t]);
            }
            float s = ((p[0] + p[1]) + (p[2] + p[3])) + ((p[4] + p[5]) + (p[6] + p[7]));

            float mn   = fmaxf(m, s);
            float corr = __expf(m - mn);
            float pw   = __expf(s - mn);
            l = l * corr + pw;
            m = mn;
#pragma unroll
            for (int d = 0; d < D_HEAD; d++)
                acc[d] = fmaf(acc[d], corr, pw * Vs[j][d]);
        }
        __syncthreads();
    }

    const float inv = 1.0f / l;
    float* yptr = &g_y[(size_t)qi * C_DIM + h * D_HEAD];
#pragma unroll
    for (int d = 0; d < D_HEAD; d += 4) {
        float4 v;
        v.x = acc[d + 0] * inv;
        v.y = acc[d + 1] * inv;
        v.z = acc[d + 2] * inv;
        v.w = acc[d + 3] * inv;
        *(float4*)&yptr[d] = v;
    }
}

// ----------------------------------------------------------------------------
// kernel_launch: 3 graph-capturable launches, no allocation, no sync.
// Inputs (metadata order): x, w_attn, b_attn, w_proj, b_proj. Output: float32.
// ----------------------------------------------------------------------------
extern "C" void kernel_launch(void* const* d_in, const int* in_sizes, int n_in,
                              void* d_out, int out_size)
{
    const float* x      = (const float*)d_in[0];
    const float* w_attn = (const float*)d_in[1];
    const float* b_attn = (const float*)d_in[2];
    const float* w_proj = (const float*)d_in[3];
    const float* b_proj = (const float*)d_in[4];
    float* out = (float*)d_out;

    float* qkv = nullptr;
    float* y   = nullptr;
    cudaGetSymbolAddress((void**)&qkv, g_qkv);
    cudaGetSymbolAddress((void**)&y, g_y);

    // 1) qkv = x @ w_attn + b_attn   [4096, 2304]
    sgemm_bias_kernel<<<dim3(QKV_N / 128, T_SEQ / 128), 256>>>(
        x, w_attn, b_attn, qkv, T_SEQ, QKV_N, C_DIM);

    // 2) causal flash attention -> y [4096, 768]
    flash_attn_kernel<<<dim3(T_SEQ / 128, H_NUM), 128>>>();

    // 3) out = y @ w_proj + b_proj   [4096, 768]
    sgemm_bias_kernel<<<dim3(C_DIM / 128, T_SEQ / 128), 256>>>(
        y, w_proj, b_proj, out, T_SEQ, C_DIM, C_DIM);
}